// round 1
// baseline (speedup 1.0000x reference)
#include <cuda_runtime.h>

#define B_ 8
#define T_ 2048
#define C_ 1024
#define H_ 64
#define M_ (B_*T_)   // 16384

// Scratch for projections (device globals: no allocation allowed)
__device__ float g_q[M_*H_];
__device__ float g_k[M_*H_];
__device__ float g_v[M_*H_];

// ---------------------------------------------------------------------------
// Fused QKV projection: y = x @ W for W in {wq,wk,wv}.
// GEMM M=16384, N=192 (q|k|v), K=1024. BM=64, BN=192, BK=32.
// 256 threads as 16x16; thread microtile 4 rows x 12 cols.
// Scale 1/sqrt(C)=1/32 folded into q at write time.
// ---------------------------------------------------------------------------
__global__ __launch_bounds__(256) void qkv_kernel(
    const float* __restrict__ x, const float* __restrict__ wq,
    const float* __restrict__ wk, const float* __restrict__ wv)
{
    __shared__ float As[64][33];    // x tile, padded
    __shared__ float Bs[32][192];   // [wq | wk | wv] tile

    const int m0  = blockIdx.x * 64;
    const int tid = threadIdx.x;
    const int tx  = tid & 15;   // 0..15 -> col group
    const int ty  = tid >> 4;   // 0..15 -> row group

    float acc[4][12];
    #pragma unroll
    for (int i = 0; i < 4; i++)
        #pragma unroll
        for (int j = 0; j < 12; j++) acc[i][j] = 0.f;

    for (int k0 = 0; k0 < C_; k0 += 32) {
        // load x tile: 64x32, coalesced (32 floats per row)
        #pragma unroll
        for (int i = tid; i < 64*32; i += 256) {
            int r = i >> 5, c = i & 31;
            As[r][c] = x[(size_t)(m0 + r) * C_ + k0 + c];
        }
        // load weight tiles: 32x64 each
        #pragma unroll
        for (int i = tid; i < 32*64; i += 256) {
            int r = i >> 6, c = i & 63;
            int gi = (k0 + r) * H_ + c;
            Bs[r][c]        = wq[gi];
            Bs[r][64 + c]   = wk[gi];
            Bs[r][128 + c]  = wv[gi];
        }
        __syncthreads();

        #pragma unroll
        for (int kk = 0; kk < 32; kk++) {
            float a[4], b[12];
            #pragma unroll
            for (int i = 0; i < 4; i++)  a[i] = As[ty*4 + i][kk];
            #pragma unroll
            for (int j = 0; j < 12; j++) b[j] = Bs[kk][tx*12 + j];
            #pragma unroll
            for (int i = 0; i < 4; i++)
                #pragma unroll
                for (int j = 0; j < 12; j++)
                    acc[i][j] += a[i] * b[j];
        }
        __syncthreads();
    }

    const float scale = 0.03125f;  // C^-0.5 folded into q
    #pragma unroll
    for (int i = 0; i < 4; i++) {
        const size_t base = (size_t)(m0 + ty*4 + i) * H_;
        #pragma unroll
        for (int j = 0; j < 12; j++) {
            int n = tx*12 + j;
            float v = acc[i][j];
            if (n < 64)        g_q[base + n]        = v * scale;
            else if (n < 128)  g_k[base + n - 64]   = v;
            else               g_v[base + n - 128]  = v;
        }
    }
}

// ---------------------------------------------------------------------------
// Flash-attention (causal), fp32, online softmax.
// Block: 64 queries x full H=64. Key tiles of 32. 256 threads (16x16).
// S microtile: 4 rows x 2 cols; O microtile: 4 rows x 4 cols (regs).
// ---------------------------------------------------------------------------
__global__ __launch_bounds__(256) void attn_kernel(float* __restrict__ out)
{
    __shared__ float Qs[64][65];
    __shared__ float Ks[32][65];
    __shared__ float Vs[32][65];
    __shared__ float Ss[64][33];
    __shared__ float m_s[64], alpha_s[64], l_s[64];

    const int qt  = blockIdx.x;   // query tile 0..31
    const int b   = blockIdx.y;   // batch 0..7
    const int tid = threadIdx.x;
    const int tx  = tid & 15;
    const int ty  = tid >> 4;

    const float* Qg = g_q + ((size_t)b * T_ + (size_t)qt * 64) * H_;
    const float* Kg = g_k + (size_t)b * T_ * H_;
    const float* Vg = g_v + (size_t)b * T_ * H_;

    #pragma unroll
    for (int i = tid; i < 64*64; i += 256) {
        int r = i >> 6, c = i & 63;
        Qs[r][c] = Qg[r * H_ + c];
    }
    if (tid < 64) { m_s[tid] = -1e30f; l_s[tid] = 0.f; }

    float O[4][4];
    #pragma unroll
    for (int i = 0; i < 4; i++)
        #pragma unroll
        for (int j = 0; j < 4; j++) O[i][j] = 0.f;

    const int q0 = qt * 64;
    const int nj = 2 * qt + 2;   // 32-key tiles up to & incl. the diagonal

    for (int j = 0; j < nj; j++) {
        __syncthreads();  // protect Ks/Vs/Ss from prior-iteration readers
        const int k0 = j * 32;

        #pragma unroll
        for (int i = tid; i < 32*64; i += 256) {
            int r = i >> 6, c = i & 63;
            Ks[r][c] = Kg[(size_t)(k0 + r) * H_ + c];
            Vs[r][c] = Vg[(size_t)(k0 + r) * H_ + c];
        }
        __syncthreads();

        // S = Q K^T (scale pre-folded into q), causal mask
        {
            const int c0 = tx * 2, c1 = c0 + 1;
            float s0[4] = {0,0,0,0}, s1[4] = {0,0,0,0};
            #pragma unroll
            for (int h = 0; h < 64; h++) {
                float bk0 = Ks[c0][h], bk1 = Ks[c1][h];
                #pragma unroll
                for (int i = 0; i < 4; i++) {
                    float a = Qs[ty*4 + i][h];
                    s0[i] += a * bk0;
                    s1[i] += a * bk1;
                }
            }
            #pragma unroll
            for (int i = 0; i < 4; i++) {
                int r  = ty*4 + i;
                int qg = q0 + r;
                Ss[r][c0] = (k0 + c0 <= qg) ? s0[i] : -1e30f;
                Ss[r][c1] = (k0 + c1 <= qg) ? s1[i] : -1e30f;
            }
        }
        __syncthreads();

        // per-row max / rescale factor (conflict-free: stride 33)
        if (tid < 64) {
            float mloc = -1e30f;
            #pragma unroll
            for (int c = 0; c < 32; c++) mloc = fmaxf(mloc, Ss[tid][c]);
            float mo = m_s[tid];
            float mn = fmaxf(mo, mloc);
            float al = __expf(mo - mn);   // 0 on first tile
            m_s[tid] = mn;
            alpha_s[tid] = al;
            l_s[tid] *= al;
        }
        __syncthreads();

        // exponentiate + rescale O accumulators
        #pragma unroll
        for (int i = 0; i < 4; i++) {
            int r = ty*4 + i;
            float mn = m_s[r];
            float p0 = __expf(Ss[r][tx*2]     - mn);
            float p1 = __expf(Ss[r][tx*2 + 1] - mn);
            Ss[r][tx*2]     = p0;
            Ss[r][tx*2 + 1] = p1;
            float al = alpha_s[r];
            #pragma unroll
            for (int jj = 0; jj < 4; jj++) O[i][jj] *= al;
        }
        __syncthreads();

        // row sums (tid<64, concurrent read-only with PV below)
        if (tid < 64) {
            float s = 0.f;
            #pragma unroll
            for (int c = 0; c < 32; c++) s += Ss[tid][c];
            l_s[tid] += s;
        }
        // O += P V
        #pragma unroll
        for (int k = 0; k < 32; k++) {
            float bv[4];
            #pragma unroll
            for (int jj = 0; jj < 4; jj++) bv[jj] = Vs[k][tx*4 + jj];
            #pragma unroll
            for (int i = 0; i < 4; i++) {
                float a = Ss[ty*4 + i][k];
                #pragma unroll
                for (int jj = 0; jj < 4; jj++) O[i][jj] += a * bv[jj];
            }
        }
    }
    __syncthreads();  // l_s final

    float* Og = out + ((size_t)b * T_ + q0) * H_;
    #pragma unroll
    for (int i = 0; i < 4; i++) {
        int r = ty*4 + i;
        float inv = 1.f / l_s[r];
        #pragma unroll
        for (int jj = 0; jj < 4; jj++)
            Og[(size_t)r * H_ + tx*4 + jj] = O[i][jj] * inv;
    }
}

extern "C" void kernel_launch(void* const* d_in, const int* in_sizes, int n_in,
                              void* d_out, int out_size)
{
    const float* x  = (const float*)d_in[0];
    const float* wq = (const float*)d_in[1];
    const float* wk = (const float*)d_in[2];
    const float* wv = (const float*)d_in[3];
    float* out = (float*)d_out;

    qkv_kernel<<<M_/64, 256>>>(x, wq, wk, wv);
    dim3 grid(T_/64, B_);
    attn_kernel<<<grid, 256>>>(out);
}

// round 2
// speedup vs baseline: 3.4153x; 3.4153x over previous
#include <cuda_runtime.h>
#include <cstdint>

#define B_ 8
#define T_ 2048
#define C_ 1024
#define H_ 64
#define M_ (B_*T_)   // 16384

// projection scratch (device globals: no allocation allowed)
__device__ float g_q[M_*H_];
__device__ float g_k[M_*H_];
__device__ float g_v[M_*H_];

__device__ __forceinline__ float tf32r(float x){
    asm("cvt.rna.tf32.f32 %0, %0;" : "+f"(x));
    return x;
}

// D = A(16x8,row) * B(8x8,col: B[k][n]) + C, tf32 in / fp32 out
__device__ __forceinline__ void mma_tf32(float* d, const float* a, const float* b, const float* c){
    asm volatile("mma.sync.aligned.m16n8k8.row.col.f32.tf32.tf32.f32 "
        "{%0,%1,%2,%3}, {%4,%5,%6,%7}, {%8,%9}, {%10,%11,%12,%13};"
        : "=f"(d[0]),"=f"(d[1]),"=f"(d[2]),"=f"(d[3])
        : "r"(__float_as_uint(a[0])),"r"(__float_as_uint(a[1])),
          "r"(__float_as_uint(a[2])),"r"(__float_as_uint(a[3])),
          "r"(__float_as_uint(b[0])),"r"(__float_as_uint(b[1])),
          "f"(c[0]),"f"(c[1]),"f"(c[2]),"f"(c[3]));
}

// ---------------------------------------------------------------------------
// Fused QKV projection: M=16384, N=192 ([q|k|v]), K=1024, tf32 mma.
// Block 64x192, 8 warps (4x2), warp tile 16x96 (12 n8 frags), K-chunk 32.
// ---------------------------------------------------------------------------
#define AS_STRIDE 36   // ≡4 mod 32 → conflict-free A frags
#define BS_STRIDE 200  // ≡8 mod 32 → conflict-free B frags

__global__ __launch_bounds__(256) void qkv_kernel(
    const float* __restrict__ x, const float* __restrict__ wq,
    const float* __restrict__ wk, const float* __restrict__ wv)
{
    __shared__ float As[64*AS_STRIDE];
    __shared__ float Bs[32*BS_STRIDE];

    const int tid  = threadIdx.x;
    const int lane = tid & 31, warp = tid >> 5;
    const int wm = warp & 3, wn = warp >> 2;
    const int g = lane >> 2, q = lane & 3;
    const int m0 = blockIdx.x * 64;

    float acc[12][4];
    #pragma unroll
    for (int j=0;j<12;j++){acc[j][0]=acc[j][1]=acc[j][2]=acc[j][3]=0.f;}

    for (int k0 = 0; k0 < C_; k0 += 32){
        __syncthreads();
        // x tile: 64x32 (2 float4 per thread)
        #pragma unroll
        for (int it=0; it<2; it++){
            int i = tid + it*256;
            int r = i>>3, c4 = (i&7)*4;
            float4 v = *(const float4*)&x[(size_t)(m0+r)*C_ + k0 + c4];
            v.x=tf32r(v.x); v.y=tf32r(v.y); v.z=tf32r(v.z); v.w=tf32r(v.w);
            *(float4*)&As[r*AS_STRIDE + c4] = v;
        }
        // weight tiles: 3 x (32x64)
        #pragma unroll
        for (int it=0; it<2; it++){
            int i = tid + it*256;
            int r = i>>4, c4 = (i&15)*4;
            int gi = (k0+r)*H_ + c4;
            float4 a = *(const float4*)&wq[gi];
            float4 bb= *(const float4*)&wk[gi];
            float4 c = *(const float4*)&wv[gi];
            a.x=tf32r(a.x); a.y=tf32r(a.y); a.z=tf32r(a.z); a.w=tf32r(a.w);
            bb.x=tf32r(bb.x); bb.y=tf32r(bb.y); bb.z=tf32r(bb.z); bb.w=tf32r(bb.w);
            c.x=tf32r(c.x); c.y=tf32r(c.y); c.z=tf32r(c.z); c.w=tf32r(c.w);
            *(float4*)&Bs[r*BS_STRIDE + c4]        = a;
            *(float4*)&Bs[r*BS_STRIDE + 64  + c4]  = bb;
            *(float4*)&Bs[r*BS_STRIDE + 128 + c4]  = c;
        }
        __syncthreads();

        #pragma unroll
        for (int kk=0;kk<4;kk++){
            float a[4];
            const int ar = (wm*16+g)*AS_STRIDE + kk*8 + q;
            a[0]=As[ar];
            a[1]=As[ar + 8*AS_STRIDE];
            a[2]=As[ar + 4];
            a[3]=As[ar + 8*AS_STRIDE + 4];
            #pragma unroll
            for (int j=0;j<12;j++){
                float b[2];
                int bc = wn*96 + j*8 + g;
                b[0]=Bs[(kk*8+q)*BS_STRIDE   + bc];
                b[1]=Bs[(kk*8+q+4)*BS_STRIDE + bc];
                mma_tf32(acc[j], a, b, acc[j]);
            }
        }
    }

    // epilogue: scatter to g_q/g_k/g_v; fold C^-0.5 into q
    #pragma unroll
    for (int j=0;j<12;j++){
        int n  = wn*96 + j*8 + q*2;
        int r0 = m0 + wm*16 + g;
        float sc   = (n < 64) ? 0.03125f : 1.f;
        float* dst = (n < 64) ? g_q : ((n < 128) ? g_k : g_v);
        int nn     = (n < 64) ? n   : ((n < 128) ? n-64 : n-128);
        dst[(size_t)r0*H_ + nn]       = acc[j][0]*sc;
        dst[(size_t)r0*H_ + nn+1]     = acc[j][1]*sc;
        dst[(size_t)(r0+8)*H_ + nn]   = acc[j][2]*sc;
        dst[(size_t)(r0+8)*H_ + nn+1] = acc[j][3]*sc;
    }
}

// ---------------------------------------------------------------------------
// Flash attention (causal), tf32 mma, online softmax in registers.
// Block: 64 queries, 4 warps (16 rows each), 64-key tiles.
// Q frags hoisted to regs; Q smem buffer reused for P.
// ---------------------------------------------------------------------------
#define PS_STRIDE 68   // ≡4 mod 32 (A-frag pattern conflict-free)
#define KS_STRIDE 68   // ≡4 mod 32 (K B-frag pattern conflict-free)
#define VS_STRIDE 72   // ≡8 mod 32 (V B-frag pattern conflict-free)
#define ATTN_SMEM ((64*PS_STRIDE + 64*KS_STRIDE + 64*VS_STRIDE)*4)

__global__ __launch_bounds__(128) void attn_kernel(float* __restrict__ out)
{
    extern __shared__ float sm[];
    float* Ps = sm;                       // Q staging, then P
    float* Ks = sm + 64*PS_STRIDE;
    float* Vs = Ks + 64*KS_STRIDE;

    const int tid  = threadIdx.x;
    const int lane = tid & 31, w = tid >> 5;
    const int g = lane >> 2, q = lane & 3;
    const int qt = 31 - blockIdx.x;       // heavy blocks launch first
    const int b  = blockIdx.y;
    const int q0 = qt * 64;

    const float* Qg = g_q + ((size_t)b*T_ + q0)*H_;
    const float* Kg = g_k + (size_t)b*T_*H_;
    const float* Vg = g_v + (size_t)b*T_*H_;

    // stage Q (tf32) into Ps buffer
    #pragma unroll
    for (int it=0; it<8; it++){
        int i = tid + it*128;
        int r = i>>4, c4 = (i&15)*4;
        float4 v = *(const float4*)&Qg[(size_t)r*H_ + c4];
        v.x=tf32r(v.x); v.y=tf32r(v.y); v.z=tf32r(v.z); v.w=tf32r(v.w);
        *(float4*)&Ps[r*PS_STRIDE + c4] = v;
    }
    __syncthreads();

    // hoist Q fragments (whole-kernel invariant)
    float qa[8][4];
    #pragma unroll
    for (int kk=0;kk<8;kk++){
        int base = (w*16+g)*PS_STRIDE + kk*8 + q;
        qa[kk][0]=Ps[base];
        qa[kk][1]=Ps[base + 8*PS_STRIDE];
        qa[kk][2]=Ps[base + 4];
        qa[kk][3]=Ps[base + 8*PS_STRIDE + 4];
    }

    float O[8][4];
    #pragma unroll
    for (int j=0;j<8;j++){O[j][0]=O[j][1]=O[j][2]=O[j][3]=0.f;}
    float m0r=-1e30f, m1r=-1e30f, l0=0.f, l1=0.f;

    const int nj = qt + 1;
    for (int jt=0; jt<nj; jt++){
        __syncthreads();                  // Ks/Vs free (and Ps from prev PV)
        const int k0 = jt*64;
        #pragma unroll
        for (int it=0; it<8; it++){
            int i = tid + it*128;
            int r = i>>4, c4 = (i&15)*4;
            float4 kv = *(const float4*)&Kg[(size_t)(k0+r)*H_ + c4];
            float4 vv = *(const float4*)&Vg[(size_t)(k0+r)*H_ + c4];
            kv.x=tf32r(kv.x); kv.y=tf32r(kv.y); kv.z=tf32r(kv.z); kv.w=tf32r(kv.w);
            vv.x=tf32r(vv.x); vv.y=tf32r(vv.y); vv.z=tf32r(vv.z); vv.w=tf32r(vv.w);
            *(float4*)&Ks[r*KS_STRIDE + c4] = kv;
            *(float4*)&Vs[r*VS_STRIDE + c4] = vv;
        }
        __syncthreads();

        // S = Q K^T (scale pre-folded into q)
        float s[8][4];
        #pragma unroll
        for (int j=0;j<8;j++){s[j][0]=s[j][1]=s[j][2]=s[j][3]=0.f;}
        #pragma unroll
        for (int kk=0;kk<8;kk++){
            #pragma unroll
            for (int j=0;j<8;j++){
                float bb[2];
                int n = j*8 + g;
                bb[0]=Ks[n*KS_STRIDE + kk*8 + q];
                bb[1]=Ks[n*KS_STRIDE + kk*8 + q + 4];
                mma_tf32(s[j], qa[kk], bb, s[j]);
            }
        }

        // causal mask (diagonal tile only; tiles aligned since Tq==Tk==64)
        if (jt == nj-1){
            #pragma unroll
            for (int j=0;j<8;j++){
                int c0 = j*8 + 2*q, c1 = c0+1;
                int r0l = w*16+g, r1l = r0l+8;
                if (c0 > r0l) s[j][0] = -1e30f;
                if (c1 > r0l) s[j][1] = -1e30f;
                if (c0 > r1l) s[j][2] = -1e30f;
                if (c1 > r1l) s[j][3] = -1e30f;
            }
        }

        // online softmax: row max via quad shuffle
        float mx0=-1e30f, mx1=-1e30f;
        #pragma unroll
        for (int j=0;j<8;j++){
            mx0 = fmaxf(mx0, fmaxf(s[j][0], s[j][1]));
            mx1 = fmaxf(mx1, fmaxf(s[j][2], s[j][3]));
        }
        mx0 = fmaxf(mx0, __shfl_xor_sync(0xffffffffu, mx0, 1));
        mx0 = fmaxf(mx0, __shfl_xor_sync(0xffffffffu, mx0, 2));
        mx1 = fmaxf(mx1, __shfl_xor_sync(0xffffffffu, mx1, 1));
        mx1 = fmaxf(mx1, __shfl_xor_sync(0xffffffffu, mx1, 2));

        float mn0 = fmaxf(m0r, mx0), mn1 = fmaxf(m1r, mx1);
        float al0 = __expf(m0r - mn0), al1 = __expf(m1r - mn1);
        m0r = mn0; m1r = mn1;
        l0 *= al0; l1 *= al1;

        float rs0=0.f, rs1=0.f;
        #pragma unroll
        for (int j=0;j<8;j++){
            float p0 = __expf(s[j][0]-mn0), p1 = __expf(s[j][1]-mn0);
            float p2 = __expf(s[j][2]-mn1), p3 = __expf(s[j][3]-mn1);
            rs0 += p0+p1; rs1 += p2+p3;
            O[j][0]*=al0; O[j][1]*=al0; O[j][2]*=al1; O[j][3]*=al1;
            int rbase = (w*16+g)*PS_STRIDE + j*8 + 2*q;
            *(float2*)&Ps[rbase]               = make_float2(tf32r(p0), tf32r(p1));
            *(float2*)&Ps[rbase + 8*PS_STRIDE] = make_float2(tf32r(p2), tf32r(p3));
        }
        rs0 += __shfl_xor_sync(0xffffffffu, rs0, 1);
        rs0 += __shfl_xor_sync(0xffffffffu, rs0, 2);
        rs1 += __shfl_xor_sync(0xffffffffu, rs1, 1);
        rs1 += __shfl_xor_sync(0xffffffffu, rs1, 2);
        l0 += rs0; l1 += rs1;

        __syncwarp();  // P rows are warp-private; warp-level fence suffices

        // O += P V
        #pragma unroll
        for (int kk=0;kk<8;kk++){
            float pa[4];
            int base = (w*16+g)*PS_STRIDE + kk*8 + q;
            pa[0]=Ps[base];
            pa[1]=Ps[base + 8*PS_STRIDE];
            pa[2]=Ps[base + 4];
            pa[3]=Ps[base + 8*PS_STRIDE + 4];
            #pragma unroll
            for (int j=0;j<8;j++){
                float bb[2];
                int h = j*8 + g;
                bb[0]=Vs[(kk*8+q)*VS_STRIDE   + h];
                bb[1]=Vs[(kk*8+q+4)*VS_STRIDE + h];
                mma_tf32(O[j], pa, bb, O[j]);
            }
        }
    }

    // epilogue
    float inv0 = 1.f/l0, inv1 = 1.f/l1;
    float* Og = out + ((size_t)b*T_ + q0 + w*16 + g)*H_;
    #pragma unroll
    for (int j=0;j<8;j++){
        *(float2*)&Og[j*8 + 2*q]        = make_float2(O[j][0]*inv0, O[j][1]*inv0);
        *(float2*)&Og[8*H_ + j*8 + 2*q] = make_float2(O[j][2]*inv1, O[j][3]*inv1);
    }
}

extern "C" void kernel_launch(void* const* d_in, const int* in_sizes, int n_in,
                              void* d_out, int out_size)
{
    const float* x  = (const float*)d_in[0];
    const float* wq = (const float*)d_in[1];
    const float* wk = (const float*)d_in[2];
    const float* wv = (const float*)d_in[3];
    float* out = (float*)d_out;

    cudaFuncSetAttribute(attn_kernel,
                         cudaFuncAttributeMaxDynamicSharedMemorySize, ATTN_SMEM);

    qkv_kernel<<<M_/64, 256>>>(x, wq, wk, wv);
    dim3 grid(T_/64, B_);
    attn_kernel<<<grid, 128, ATTN_SMEM>>>(out);
}

// round 3
// speedup vs baseline: 4.3702x; 1.2796x over previous
#include <cuda_runtime.h>
#include <cstdint>

#define B_ 8
#define T_ 2048
#define C_ 1024
#define H_ 64
#define M_ (B_*T_)   // 16384

__device__ float g_q[M_*H_];
__device__ float g_k[M_*H_];
__device__ float g_v[M_*H_];

__device__ __forceinline__ float tf32r(float x){
    asm("cvt.rna.tf32.f32 %0, %0;" : "+f"(x));
    return x;
}
__device__ __forceinline__ float4 tf32r4(float4 v){
    v.x=tf32r(v.x); v.y=tf32r(v.y); v.z=tf32r(v.z); v.w=tf32r(v.w);
    return v;
}

__device__ __forceinline__ void mma_tf32(float* d, const float* a, const float* b, const float* c){
    asm volatile("mma.sync.aligned.m16n8k8.row.col.f32.tf32.tf32.f32 "
        "{%0,%1,%2,%3}, {%4,%5,%6,%7}, {%8,%9}, {%10,%11,%12,%13};"
        : "=f"(d[0]),"=f"(d[1]),"=f"(d[2]),"=f"(d[3])
        : "r"(__float_as_uint(a[0])),"r"(__float_as_uint(a[1])),
          "r"(__float_as_uint(a[2])),"r"(__float_as_uint(a[3])),
          "r"(__float_as_uint(b[0])),"r"(__float_as_uint(b[1])),
          "f"(c[0]),"f"(c[1]),"f"(c[2]),"f"(c[3]));
}

// ---------------------------------------------------------------------------
// Fused QKV projection, tf32 mma, double-buffered (register-staged) pipeline.
// BM=128, BN=192, BK=32. 8 warps (4x2), warp tile 32x96. Grid = 128 CTAs.
// ---------------------------------------------------------------------------
#define AS_STRIDE 36   // ≡4 mod 32
#define BS_STRIDE 200  // ≡8 mod 32
#define QKV_SMEM ((2*128*AS_STRIDE + 2*32*BS_STRIDE)*4)

__global__ __launch_bounds__(256) void qkv_kernel(
    const float* __restrict__ x, const float* __restrict__ wq,
    const float* __restrict__ wk, const float* __restrict__ wv)
{
    extern __shared__ float sm[];
    float* Asm = sm;                        // 2 x 128*AS_STRIDE
    float* Bsm = sm + 2*128*AS_STRIDE;      // 2 x 32*BS_STRIDE

    const int tid  = threadIdx.x;
    const int lane = tid & 31, warp = tid >> 5;
    const int wm = warp & 3, wn = warp >> 2;
    const int g = lane >> 2, q = lane & 3;
    const int m0 = blockIdx.x * 128;

    float acc[2][12][4];
    #pragma unroll
    for (int mi=0;mi<2;mi++)
        #pragma unroll
        for (int j=0;j<12;j++){acc[mi][j][0]=acc[mi][j][1]=acc[mi][j][2]=acc[mi][j][3]=0.f;}

    float4 xs[4], ws[3][2];

#define QKV_LOAD(K0) do { \
    _Pragma("unroll") \
    for (int it=0; it<4; it++){ \
        int i = tid + it*256; int r = i>>3, c4 = (i&7)*4; \
        xs[it] = *(const float4*)&x[(size_t)(m0+r)*C_ + (K0) + c4]; \
    } \
    _Pragma("unroll") \
    for (int it=0; it<2; it++){ \
        int i = tid + it*256; int r = i>>4, c4 = (i&15)*4; \
        int gi = ((K0)+r)*H_ + c4; \
        ws[0][it] = *(const float4*)&wq[gi]; \
        ws[1][it] = *(const float4*)&wk[gi]; \
        ws[2][it] = *(const float4*)&wv[gi]; \
    } } while(0)

#define QKV_STORE(BUF) do { \
    float* A = Asm + (BUF)*128*AS_STRIDE; \
    float* Bb = Bsm + (BUF)*32*BS_STRIDE; \
    _Pragma("unroll") \
    for (int it=0; it<4; it++){ \
        int i = tid + it*256; int r = i>>3, c4 = (i&7)*4; \
        *(float4*)&A[r*AS_STRIDE + c4] = tf32r4(xs[it]); \
    } \
    _Pragma("unroll") \
    for (int it=0; it<2; it++){ \
        int i = tid + it*256; int r = i>>4, c4 = (i&15)*4; \
        *(float4*)&Bb[r*BS_STRIDE + c4]       = tf32r4(ws[0][it]); \
        *(float4*)&Bb[r*BS_STRIDE + 64 + c4]  = tf32r4(ws[1][it]); \
        *(float4*)&Bb[r*BS_STRIDE + 128 + c4] = tf32r4(ws[2][it]); \
    } } while(0)

#define QKV_COMPUTE(BUF) do { \
    const float* A = Asm + (BUF)*128*AS_STRIDE; \
    const float* Bb = Bsm + (BUF)*32*BS_STRIDE; \
    _Pragma("unroll") \
    for (int kk=0;kk<4;kk++){ \
        float a[2][4]; \
        _Pragma("unroll") \
        for (int mi=0;mi<2;mi++){ \
            int base = (wm*32 + mi*16 + g)*AS_STRIDE + kk*8 + q; \
            a[mi][0]=A[base]; a[mi][1]=A[base + 8*AS_STRIDE]; \
            a[mi][2]=A[base+4]; a[mi][3]=A[base + 8*AS_STRIDE + 4]; \
        } \
        _Pragma("unroll") \
        for (int j=0;j<12;j++){ \
            float b[2]; int bc = wn*96 + j*8 + g; \
            b[0]=Bb[(kk*8+q)*BS_STRIDE + bc]; \
            b[1]=Bb[(kk*8+q+4)*BS_STRIDE + bc]; \
            mma_tf32(acc[0][j], a[0], b, acc[0][j]); \
            mma_tf32(acc[1][j], a[1], b, acc[1][j]); \
        } \
    } } while(0)

    QKV_LOAD(0);
    QKV_STORE(0);
    __syncthreads();

    #pragma unroll 1
    for (int c = 0; c < 32; c++){
        const int cur = c & 1;
        if (c < 31) QKV_LOAD((c+1) << 5);
        QKV_COMPUTE(cur);
        if (c < 31){
            QKV_STORE(cur ^ 1);
            __syncthreads();
        }
    }

    // epilogue: scatter to g_q/g_k/g_v; fold C^-0.5 into q
    #pragma unroll
    for (int mi=0;mi<2;mi++){
        #pragma unroll
        for (int j=0;j<12;j++){
            int n  = wn*96 + j*8 + q*2;
            int r0 = m0 + wm*32 + mi*16 + g;
            float sc   = (n < 64) ? 0.03125f : 1.f;
            float* dst = (n < 64) ? g_q : ((n < 128) ? g_k : g_v);
            int nn     = (n < 64) ? n   : ((n < 128) ? n-64 : n-128);
            *(float2*)&dst[(size_t)r0*H_ + nn]     = make_float2(acc[mi][j][0]*sc, acc[mi][j][1]*sc);
            *(float2*)&dst[(size_t)(r0+8)*H_ + nn] = make_float2(acc[mi][j][2]*sc, acc[mi][j][3]*sc);
        }
    }
}

// ---------------------------------------------------------------------------
// Flash attention (causal), tf32 mma, 8 warps, intra-CTA split-K by 2:
// warp-group 0 (warps 0-3) processes even key tiles, group 1 odd tiles,
// each with private K/V/P smem buffers + named barriers; merged at the end.
// ---------------------------------------------------------------------------
#define PS_STRIDE 68
#define KS_STRIDE 68
#define VS_STRIDE 72
// floats: Qs/P0 @0 (64*68), P1 @4352, K0 @8704, V0 @13056, K1 @17664, V1 @22016
#define ATTN_SMEM (26624*4)

__global__ __launch_bounds__(256) void attn_kernel(float* __restrict__ out)
{
    extern __shared__ float sm[];

    const int tid  = threadIdx.x;
    const int lane = tid & 31, w = tid >> 5;
    const int g = lane >> 2, q = lane & 3;
    const int h  = w >> 2;        // key-parity group
    const int wr = w & 3;         // row warp within group (16 rows)
    const int qt = 31 - blockIdx.x;
    const int b  = blockIdx.y;
    const int q0 = qt * 64;
    const int nj = qt + 1;

    float* Qs = sm;                          // also P for group 0
    float* Ps = sm + (h ? 4352 : 0);
    float* Ks = sm + 8704 + h*8960;
    float* Vs = Ks + 4352;

    const float* Qg = g_q + ((size_t)b*T_ + q0)*H_;
    const float* Kg = g_k + (size_t)b*T_*H_;
    const float* Vg = g_v + (size_t)b*T_*H_;

    // stage Q (all 256 threads)
    #pragma unroll
    for (int it=0; it<4; it++){
        int i = tid + it*256;
        int r = i>>4, c4 = (i&15)*4;
        *(float4*)&Qs[r*PS_STRIDE + c4] = tf32r4(*(const float4*)&Qg[(size_t)r*H_ + c4]);
    }
    __syncthreads();

    // hoist Q fragments (rows wr*16 .. +16, full H)
    float qa[8][4];
    #pragma unroll
    for (int kk=0;kk<8;kk++){
        int base = (wr*16+g)*PS_STRIDE + kk*8 + q;
        qa[kk][0]=Qs[base];
        qa[kk][1]=Qs[base + 8*PS_STRIDE];
        qa[kk][2]=Qs[base + 4];
        qa[kk][3]=Qs[base + 8*PS_STRIDE + 4];
    }
    __syncthreads();   // Qs now reusable as P0

    float O[8][4];
    #pragma unroll
    for (int j=0;j<8;j++){O[j][0]=O[j][1]=O[j][2]=O[j][3]=0.f;}
    float m0r=-1e30f, m1r=-1e30f, l0=0.f, l1=0.f;

    const int gtid = wr*32 + lane;   // 0..127 within group

    #pragma unroll 1
    for (int jt = h; jt < nj; jt += 2){
        asm volatile("bar.sync %0, 128;" :: "r"(1+h) : "memory");
        const int k0 = jt*64;
        #pragma unroll
        for (int it=0; it<8; it++){
            int i = gtid + it*128;
            int r = i>>4, c4 = (i&15)*4;
            *(float4*)&Ks[r*KS_STRIDE + c4] = tf32r4(*(const float4*)&Kg[(size_t)(k0+r)*H_ + c4]);
            *(float4*)&Vs[r*VS_STRIDE + c4] = tf32r4(*(const float4*)&Vg[(size_t)(k0+r)*H_ + c4]);
        }
        asm volatile("bar.sync %0, 128;" :: "r"(1+h) : "memory");

        // S = Q K^T (scale folded into q)
        float s[8][4];
        #pragma unroll
        for (int j=0;j<8;j++){s[j][0]=s[j][1]=s[j][2]=s[j][3]=0.f;}
        #pragma unroll
        for (int kk=0;kk<8;kk++){
            #pragma unroll
            for (int j=0;j<8;j++){
                float bb[2];
                int n = j*8 + g;
                bb[0]=Ks[n*KS_STRIDE + kk*8 + q];
                bb[1]=Ks[n*KS_STRIDE + kk*8 + q + 4];
                mma_tf32(s[j], qa[kk], bb, s[j]);
            }
        }

        if (jt == nj-1){  // diagonal tile → causal mask (tile-aligned)
            #pragma unroll
            for (int j=0;j<8;j++){
                int c0 = j*8 + 2*q, c1 = c0+1;
                int r0l = wr*16+g, r1l = r0l+8;
                if (c0 > r0l) s[j][0] = -1e30f;
                if (c1 > r0l) s[j][1] = -1e30f;
                if (c0 > r1l) s[j][2] = -1e30f;
                if (c1 > r1l) s[j][3] = -1e30f;
            }
        }

        // online softmax (registers + quad shuffles)
        float mx0=-1e30f, mx1=-1e30f;
        #pragma unroll
        for (int j=0;j<8;j++){
            mx0 = fmaxf(mx0, fmaxf(s[j][0], s[j][1]));
            mx1 = fmaxf(mx1, fmaxf(s[j][2], s[j][3]));
        }
        mx0 = fmaxf(mx0, __shfl_xor_sync(0xffffffffu, mx0, 1));
        mx0 = fmaxf(mx0, __shfl_xor_sync(0xffffffffu, mx0, 2));
        mx1 = fmaxf(mx1, __shfl_xor_sync(0xffffffffu, mx1, 1));
        mx1 = fmaxf(mx1, __shfl_xor_sync(0xffffffffu, mx1, 2));

        float mn0 = fmaxf(m0r, mx0), mn1 = fmaxf(m1r, mx1);
        float al0 = __expf(m0r - mn0), al1 = __expf(m1r - mn1);
        m0r = mn0; m1r = mn1;
        l0 *= al0; l1 *= al1;

        float rs0=0.f, rs1=0.f;
        #pragma unroll
        for (int j=0;j<8;j++){
            float p0 = __expf(s[j][0]-mn0), p1 = __expf(s[j][1]-mn0);
            float p2 = __expf(s[j][2]-mn1), p3 = __expf(s[j][3]-mn1);
            rs0 += p0+p1; rs1 += p2+p3;
            O[j][0]*=al0; O[j][1]*=al0; O[j][2]*=al1; O[j][3]*=al1;
            int rbase = (wr*16+g)*PS_STRIDE + j*8 + 2*q;
            *(float2*)&Ps[rbase]               = make_float2(tf32r(p0), tf32r(p1));
            *(float2*)&Ps[rbase + 8*PS_STRIDE] = make_float2(tf32r(p2), tf32r(p3));
        }
        rs0 += __shfl_xor_sync(0xffffffffu, rs0, 1);
        rs0 += __shfl_xor_sync(0xffffffffu, rs0, 2);
        rs1 += __shfl_xor_sync(0xffffffffu, rs1, 1);
        rs1 += __shfl_xor_sync(0xffffffffu, rs1, 2);
        l0 += rs0; l1 += rs1;

        __syncwarp();   // P rows are warp-private

        // O += P V
        #pragma unroll
        for (int kk=0;kk<8;kk++){
            float pa[4];
            int base = (wr*16+g)*PS_STRIDE + kk*8 + q;
            pa[0]=Ps[base];
            pa[1]=Ps[base + 8*PS_STRIDE];
            pa[2]=Ps[base + 4];
            pa[3]=Ps[base + 8*PS_STRIDE + 4];
            #pragma unroll
            for (int j=0;j<8;j++){
                float bb[2];
                int hh = j*8 + g;
                bb[0]=Vs[(kk*8+q)*VS_STRIDE   + hh];
                bb[1]=Vs[(kk*8+q+4)*VS_STRIDE + hh];
                mma_tf32(O[j], pa, bb, O[j]);
            }
        }
    }

    // merge the two key-parity partials
    __syncthreads();
    float* mb = sm + 8704;   // 128*36 floats, overlays K0/V0 (dead now)
    const int slot = (wr*32 + lane)*36;
    if (h == 1){
        #pragma unroll
        for (int j=0;j<8;j++){
            mb[slot+j*4+0]=O[j][0]; mb[slot+j*4+1]=O[j][1];
            mb[slot+j*4+2]=O[j][2]; mb[slot+j*4+3]=O[j][3];
        }
        mb[slot+32]=m0r; mb[slot+33]=m1r; mb[slot+34]=l0; mb[slot+35]=l1;
    }
    __syncthreads();
    if (h == 0){
        float m0o = mb[slot+32], m1o = mb[slot+33];
        float l0o = mb[slot+34], l1o = mb[slot+35];
        float M0 = fmaxf(m0r, m0o), M1 = fmaxf(m1r, m1o);
        float a0 = __expf(m0r-M0), b0 = __expf(m0o-M0);
        float a1 = __expf(m1r-M1), b1 = __expf(m1o-M1);
        float inv0 = 1.f/(l0*a0 + l0o*b0);
        float inv1 = 1.f/(l1*a1 + l1o*b1);
        float* Og = out + ((size_t)b*T_ + q0 + wr*16 + g)*H_;
        #pragma unroll
        for (int j=0;j<8;j++){
            float o0 = (O[j][0]*a0 + mb[slot+j*4+0]*b0)*inv0;
            float o1 = (O[j][1]*a0 + mb[slot+j*4+1]*b0)*inv0;
            float o2 = (O[j][2]*a1 + mb[slot+j*4+2]*b1)*inv1;
            float o3 = (O[j][3]*a1 + mb[slot+j*4+3]*b1)*inv1;
            *(float2*)&Og[j*8 + 2*q]        = make_float2(o0, o1);
            *(float2*)&Og[8*H_ + j*8 + 2*q] = make_float2(o2, o3);
        }
    }
}

extern "C" void kernel_launch(void* const* d_in, const int* in_sizes, int n_in,
                              void* d_out, int out_size)
{
    const float* x  = (const float*)d_in[0];
    const float* wq = (const float*)d_in[1];
    const float* wk = (const float*)d_in[2];
    const float* wv = (const float*)d_in[3];
    float* out = (float*)d_out;

    cudaFuncSetAttribute(qkv_kernel,
                         cudaFuncAttributeMaxDynamicSharedMemorySize, QKV_SMEM);
    cudaFuncSetAttribute(attn_kernel,
                         cudaFuncAttributeMaxDynamicSharedMemorySize, ATTN_SMEM);

    qkv_kernel<<<M_/128, 256, QKV_SMEM>>>(x, wq, wk, wv);
    dim3 grid(T_/64, B_);
    attn_kernel<<<grid, 256, ATTN_SMEM>>>(out);
}